// round 14
// baseline (speedup 1.0000x reference)
#include <cuda_runtime.h>
#include <math.h>
#include <float.h>

#define Bn 32
#define Ln 512
#define Nn 1024
#define Dn 64
#define TK 20
#define NNODE 32768           // B*N = 32*1024 (== L*64)
#define BN_EPS 1e-5f

typedef unsigned long long ull;

// ---------------- scratch (static device globals; no allocation) ----------------
__device__ __align__(16) float4 g_ps4 [8*8192];   // partial sums  (8 l-chunks, float4 over n)
__device__ __align__(16) float4 g_psq4[8*8192];   // partial sumsq
__device__ __align__(16) float  g_scale[NNODE];   // rstd per (b,n)
__device__ __align__(16) float  g_shift[NNODE];   // -mean*rstd
__device__ __align__(16) float  g_S   [64*64];    // shift @ W bias (per (b-half) row, per d)
__device__ __align__(16) float  g_h  [NNODE*Dn];  // GEMM output (8MB)
__device__ float  g_cos[Nn*Nn];       // cosine matrix (4MB)
__device__ float  g_nrm[Nn];
__device__ float  g_ei [Nn];
__device__ float  g_ej [Nn];
__device__ int    g_topk[Nn*TK];
__device__ float  g_ai [NNODE];
__device__ float  g_aj [NNODE];
__device__ float  g_out[NNODE*Dn];    // aggregated (8MB)
__device__ float  g_p1 [256*2*Dn];    // BN1 block partials [256][128]
__device__ float  g_p2 [512*2*Dn];    // BN2 block partials [512][128]
__device__ float  g_bn1f[2*Dn];       // BN1 scale/shift
__device__ float  g_bn2f[2*Dn];       // BN2 scale/shift

// ---------------- K1: per-(b,n) sum/sumsq over L (vectorized, l-split) ----------
__global__ __launch_bounds__(256) void k1_stats(const float* __restrict__ x) {
    int nb = blockIdx.x;                       // 4  (n-chunk of 256)
    int b  = blockIdx.y;                       // 32
    int lc = blockIdx.z;                       // 8  (l-chunk of 64)
    int g  = threadIdx.x & 63;                 // float4 group over n
    int lq = threadIdx.x >> 6;                 // 4 l-slices of 16
    const float4* p = (const float4*)(x + ((size_t)b * Ln + (size_t)lc * 64 + lq * 16) * Nn
                                        + nb * 256 + g * 4);
    float4 s4 = make_float4(0.f, 0.f, 0.f, 0.f);
    float4 q4 = make_float4(0.f, 0.f, 0.f, 0.f);
#pragma unroll
    for (int i = 0; i < 16; i++) {
        float4 v = p[(size_t)i * (Nn / 4)];
        s4.x += v.x; s4.y += v.y; s4.z += v.z; s4.w += v.w;
        q4.x += v.x * v.x; q4.y += v.y * v.y; q4.z += v.z * v.z; q4.w += v.w * v.w;
    }
    __shared__ float4 ss[4][64], qq[4][64];
    ss[lq][g] = s4; qq[lq][g] = q4;
    __syncthreads();
    if (threadIdx.x < 64) {
        int i = threadIdx.x;
        float4 a0 = ss[0][i], a1 = ss[1][i], a2 = ss[2][i], a3 = ss[3][i];
        float4 b0 = qq[0][i], b1 = qq[1][i], b2 = qq[2][i], b3 = qq[3][i];
        float4 S = make_float4(a0.x+a1.x+a2.x+a3.x, a0.y+a1.y+a2.y+a3.y,
                               a0.z+a1.z+a2.z+a3.z, a0.w+a1.w+a2.w+a3.w);
        float4 Q = make_float4(b0.x+b1.x+b2.x+b3.x, b0.y+b1.y+b2.y+b3.y,
                               b0.z+b1.z+b2.z+b3.z, b0.w+b1.w+b2.w+b3.w);
        int m4 = b * 256 + nb * 64 + i;
        g_ps4 [lc * 8192 + m4] = S;
        g_psq4[lc * 8192 + m4] = Q;
    }
}

// ---------------- K1b: finalize scale/shift + write gt -------------------------
__global__ __launch_bounds__(256) void k1b_fin(const float* __restrict__ x,
                                               float* __restrict__ dout) {
    int m = blockIdx.x * 256 + threadIdx.x;    // 128 blocks -> 32768
    const float* psF = (const float*)g_ps4;
    const float* qqF = (const float*)g_psq4;
    float s = 0.f, sq = 0.f;
#pragma unroll
    for (int lc = 0; lc < 8; lc++) { s += psF[lc * 32768 + m]; sq += qqF[lc * 32768 + m]; }
    float mean = s * (1.f / 512.f);
    float var  = sq * (1.f / 512.f) - mean * mean;   // NO eps (matches reference)
    float rstd = 1.f / sqrtf(var);
    g_scale[m] = rstd;
    g_shift[m] = -mean * rstd;
    int b = m >> 10, n = m & 1023;
    float xl = x[(size_t)b * Ln * Nn + (size_t)(Ln - 1) * Nn + n];
    float gv = xl * rstd - mean * rstd;
    if (!isfinite(gv)) gv = 0.f;                     // nan_to_num
    dout[NNODE + m] = gv;                            // gt is second half of output
}

// ---------------- K1c: S[c][d] = sum_k shift[c*512+k] * W[k][d] ----------------
__global__ __launch_bounds__(256) void k1c_S(const float* __restrict__ W) {
    int c = blockIdx.x;                        // 64
    int d = threadIdx.x & 63, kq = threadIdx.x >> 6;
    float acc = 0.f;
    for (int k = kq * 128; k < kq * 128 + 128; k++)
        acc = fmaf(g_shift[c * 512 + k], W[k * 64 + d], acc);
    __shared__ float rs[4][64];
    rs[kq][d] = acc;
    __syncthreads();
    if (threadIdx.x < 64)
        g_S[c * 64 + threadIdx.x] = rs[0][threadIdx.x] + rs[1][threadIdx.x]
                                  + rs[2][threadIdx.x] + rs[3][threadIdx.x];
}

// ---------------- K2: h = x*scale @ W + S  + fused ai/aj epilogue --------------
#define FMA2(d, a, b) asm("fma.rn.f32x2 %0, %1, %2, %0;" : "+l"(d) : "l"(a), "l"(b))
#define PACKDUP(d, v) asm("mov.b64 %0, {%1, %1};" : "=l"(d) : "r"(__float_as_uint(v)))

__global__ __launch_bounds__(256) void k2_gemm(const float* __restrict__ x,
                                               const float* __restrict__ W,
                                               const float* __restrict__ ati,
                                               const float* __restrict__ atj) {
    int l = blockIdx.x;                        // 512 (row-tile = timestep slice)
    int tid = threadIdx.x;
    if (l == Ln - 1) {                          // enc last timestep zeroed -> h rows = 0
        for (int a = tid; a < 64 * 64; a += 256)
            g_h[(size_t)l * 64 * 64 + a] = 0.f;
        if (tid < 64) { g_ai[l * 64 + tid] = 0.f; g_aj[l * 64 + tid] = 0.f; }
        return;
    }
    // A: [64 rows][32 k] scalar, pad 36.  B: [32 k][32 col-pairs] f32x2.  2 buffers.
    __shared__ __align__(16) float As[2][64][36];
    __shared__ __align__(16) ull   Bs[2][32][32];
    ull acc2[4][2] = {};                        // acc2[r][p] = cols (tx*4+2p, tx*4+2p+1)
    int ty = tid >> 4, tx = tid & 15;

    float4 xv[2], sv[2], wv[2], xv2[2], sv2[2], wv2[2];

    // ---- vectorized tile loader: per thread 2 x-float4 + 2 sc-float4 + 2 W-float4
    auto load_tile = [&](int kt, float4* xr, float4* sr, float4* wr) {
#pragma unroll
        for (int r = 0; r < 2; r++) {
            int a = tid + r * 256;              // [0, 512)
            int c = a >> 3, ch = a & 7;         // A: row c, k-chunk ch (4 floats)
            int m = c * 512 + kt * 32 + ch * 4; // flat node idx of first k
            int bb = m >> 10, nn = m & 1023;
            xr[r] = *(const float4*)(x + (size_t)bb * (Ln * Nn) + (size_t)l * Nn + nn);
            sr[r] = *(const float4*)(g_scale + m);
            int k2i = a >> 4, dq = a & 15;      // W: k row k2i, col-chunk dq (4 floats)
            wr[r] = *(const float4*)(W + (size_t)(kt * 32 + k2i) * 64 + dq * 4);
        }
    };
    auto store_tile = [&](int buf, const float4* xr, const float4* sr, const float4* wr) {
#pragma unroll
        for (int r = 0; r < 2; r++) {
            int a = tid + r * 256;
            int c = a >> 3, ch = a & 7;
            float4 v = make_float4(xr[r].x * sr[r].x, xr[r].y * sr[r].y,
                                   xr[r].z * sr[r].z, xr[r].w * sr[r].w);
            *(float4*)&As[buf][c][ch * 4] = v;
            int k2i = a >> 4, dq = a & 15;
            *(float4*)((float*)&Bs[buf][k2i][0] + dq * 4) = wr[r];
        }
    };

    load_tile(0, xv, sv, wv);
    store_tile(0, xv, sv, wv);
    __syncthreads();

    for (int kt = 0; kt < 16; kt++) {
        int buf = kt & 1;
        if (kt < 15) load_tile(kt + 1, xv2, sv2, wv2);   // prefetch overlaps compute

        const float (*Asb)[36] = As[buf];
        const ull   (*Bsb)[32] = Bs[buf];
#pragma unroll
        for (int jq = 0; jq < 32; jq += 4) {
            float4 A0 = *(const float4*)&Asb[ty * 4 + 0][jq];
            float4 A1 = *(const float4*)&Asb[ty * 4 + 1][jq];
            float4 A2 = *(const float4*)&Asb[ty * 4 + 2][jq];
            float4 A3 = *(const float4*)&Asb[ty * 4 + 3][jq];
            ulonglong2 B0 = *(const ulonglong2*)&Bsb[jq + 0][tx * 2];
            ulonglong2 B1 = *(const ulonglong2*)&Bsb[jq + 1][tx * 2];
            ulonglong2 B2 = *(const ulonglong2*)&Bsb[jq + 2][tx * 2];
            ulonglong2 B3 = *(const ulonglong2*)&Bsb[jq + 3][tx * 2];
            ull aa;
            PACKDUP(aa, A0.x); FMA2(acc2[0][0], aa, B0.x); FMA2(acc2[0][1], aa, B0.y);
            PACKDUP(aa, A1.x); FMA2(acc2[1][0], aa, B0.x); FMA2(acc2[1][1], aa, B0.y);
            PACKDUP(aa, A2.x); FMA2(acc2[2][0], aa, B0.x); FMA2(acc2[2][1], aa, B0.y);
            PACKDUP(aa, A3.x); FMA2(acc2[3][0], aa, B0.x); FMA2(acc2[3][1], aa, B0.y);
            PACKDUP(aa, A0.y); FMA2(acc2[0][0], aa, B1.x); FMA2(acc2[0][1], aa, B1.y);
            PACKDUP(aa, A1.y); FMA2(acc2[1][0], aa, B1.x); FMA2(acc2[1][1], aa, B1.y);
            PACKDUP(aa, A2.y); FMA2(acc2[2][0], aa, B1.x); FMA2(acc2[2][1], aa, B1.y);
            PACKDUP(aa, A3.y); FMA2(acc2[3][0], aa, B1.x); FMA2(acc2[3][1], aa, B1.y);
            PACKDUP(aa, A0.z); FMA2(acc2[0][0], aa, B2.x); FMA2(acc2[0][1], aa, B2.y);
            PACKDUP(aa, A1.z); FMA2(acc2[1][0], aa, B2.x); FMA2(acc2[1][1], aa, B2.y);
            PACKDUP(aa, A2.z); FMA2(acc2[2][0], aa, B2.x); FMA2(acc2[2][1], aa, B2.y);
            PACKDUP(aa, A3.z); FMA2(acc2[3][0], aa, B2.x); FMA2(acc2[3][1], aa, B2.y);
            PACKDUP(aa, A0.w); FMA2(acc2[0][0], aa, B3.x); FMA2(acc2[0][1], aa, B3.y);
            PACKDUP(aa, A1.w); FMA2(acc2[1][0], aa, B3.x); FMA2(acc2[1][1], aa, B3.y);
            PACKDUP(aa, A2.w); FMA2(acc2[2][0], aa, B3.x); FMA2(acc2[2][1], aa, B3.y);
            PACKDUP(aa, A3.w); FMA2(acc2[3][0], aa, B3.x); FMA2(acc2[3][1], aa, B3.y);
        }
        __syncthreads();                        // all reads of buf done
        if (kt < 15) {
            store_tile(buf ^ 1, xv2, sv2, wv2); // write other buffer
            __syncthreads();                    // publish before next compute
        }
    }
    // ---- add hoisted shift bias S, write h, fused ai/aj dots ----
    float4 wi = *(const float4*)&ati[tx * 4];
    float4 wj = *(const float4*)&atj[tx * 4];
#pragma unroll
    for (int r = 0; r < 4; r++) {
        int row = ty * 4 + r;
        float4 Sb = *(const float4*)&g_S[row * 64 + tx * 4];
        float2 p0 = *(float2*)&acc2[r][0];
        float2 p1 = *(float2*)&acc2[r][1];
        float4 o = make_float4(p0.x + Sb.x, p0.y + Sb.y, p1.x + Sb.z, p1.y + Sb.w);
        *(float4*)&g_h[((size_t)l * 64 + row) * 64 + tx * 4] = o;
        float di = o.x * wi.x + o.y * wi.y + o.z * wi.z + o.w * wi.w;
        float dj = o.x * wj.x + o.y * wj.y + o.z * wj.z + o.w * wj.w;
#pragma unroll
        for (int off = 8; off; off >>= 1) {
            di += __shfl_xor_sync(0xffffffffu, di, off);
            dj += __shfl_xor_sync(0xffffffffu, dj, off);
        }
        if (tx == 0) {
            g_ai[l * 64 + row] = di;
            g_aj[l * 64 + row] = dj;
        }
    }
}

// ---------------- K3a: emb norms + att_em dots (warp per n) --------------------
__global__ __launch_bounds__(256) void k3a_emb(const float* __restrict__ emb,
                                               const float* __restrict__ aei,
                                               const float* __restrict__ aej) {
    int w = (blockIdx.x * 256 + threadIdx.x) >> 5;  // 128 blocks -> 1024 warps
    int lane = threadIdx.x & 31;
    float e1 = emb[w * 64 + lane], e2 = emb[w * 64 + 32 + lane];
    float sq = e1 * e1 + e2 * e2;
    float di = e1 * aei[lane] + e2 * aei[lane + 32];
    float dj = e1 * aej[lane] + e2 * aej[lane + 32];
#pragma unroll
    for (int off = 16; off; off >>= 1) {
        sq += __shfl_xor_sync(0xffffffffu, sq, off);
        di += __shfl_xor_sync(0xffffffffu, di, off);
        dj += __shfl_xor_sync(0xffffffffu, dj, off);
    }
    if (lane == 0) { g_nrm[w] = sqrtf(sq); g_ei[w] = di; g_ej[w] = dj; }
}

// ---------------- K3b1: cosine matrix (64x64 tiles) ----------------------------
__global__ __launch_bounds__(256) void k3b1_cos(const float* __restrict__ emb) {
    __shared__ float Ae[64][65];
    __shared__ float Be[64][65];
    int tid = threadIdx.x;
    int by = blockIdx.y, bx = blockIdx.x;
#pragma unroll
    for (int r = 0; r < 16; r++) {
        int a = tid + r * 256;
        int row = a >> 6, col = a & 63;
        Ae[row][col] = emb[(by * 64 + row) * 64 + col];
        Be[row][col] = emb[(bx * 64 + row) * 64 + col];
    }
    __syncthreads();
    int ty = tid >> 4, tx = tid & 15;
    float acc[4][4] = {};
#pragma unroll 8
    for (int d = 0; d < 64; d++) {
        float av[4], bv[4];
#pragma unroll
        for (int r = 0; r < 4; r++) { av[r] = Ae[ty * 4 + r][d]; bv[r] = Be[tx * 4 + r][d]; }
#pragma unroll
        for (int r = 0; r < 4; r++)
#pragma unroll
            for (int s2 = 0; s2 < 4; s2++)
                acc[r][s2] = fmaf(av[r], bv[s2], acc[r][s2]);
    }
#pragma unroll
    for (int r = 0; r < 4; r++)
#pragma unroll
        for (int s2 = 0; s2 < 4; s2++) {
            int rg = by * 64 + ty * 4 + r, cg = bx * 64 + tx * 4 + s2;
            g_cos[rg * 1024 + cg] = acc[r][s2] / (g_nrm[rg] * g_nrm[cg]);
        }
}

// ---------------- K3b2: top-20 per row, shuffle argmax (JAX tie rule) -----------
__global__ __launch_bounds__(1024) void k3b2_topk() {
    int r = blockIdx.x, t = threadIdx.x;
    int lane = t & 31, wid = t >> 5;
    __shared__ float swv[32];
    __shared__ int   swi[32];
    __shared__ int   s_best;
    float v = g_cos[r * 1024 + t];
#pragma unroll 1
    for (int it = 0; it < TK; it++) {
        float mv = v; int mi = t;
#pragma unroll
        for (int off = 16; off; off >>= 1) {
            float ov = __shfl_xor_sync(0xffffffffu, mv, off);
            int   oi = __shfl_xor_sync(0xffffffffu, mi, off);
            if (ov > mv || (ov == mv && oi < mi)) { mv = ov; mi = oi; }
        }
        if (lane == 0) { swv[wid] = mv; swi[wid] = mi; }
        __syncthreads();
        if (wid == 0) {
            float mv2 = swv[lane]; int mi2 = swi[lane];
#pragma unroll
            for (int off = 16; off; off >>= 1) {
                float ov = __shfl_xor_sync(0xffffffffu, mv2, off);
                int   oi = __shfl_xor_sync(0xffffffffu, mi2, off);
                if (ov > mv2 || (ov == mv2 && oi < mi2)) { mv2 = ov; mi2 = oi; }
            }
            if (lane == 0) { g_topk[r * TK + it] = mi2; s_best = mi2; }
        }
        __syncthreads();
        if (t == s_best) v = -FLT_MAX;
    }
}

// ---------------- K4: per-node attention softmax + aggregation -----------------
__global__ __launch_bounds__(256) void k4_agg(const float* __restrict__ gnnb) {
    int grp = threadIdx.x >> 6;                 // 4 dst nodes / block
    int t   = threadIdx.x & 63;
    int v = blockIdx.x * 4 + grp;               // 8192 blocks
    int b = v >> 10, n = v & 1023;
    __shared__ float s_al[4][21];
    __shared__ int   s_sr[4][21];
    if (t < 32) {
        int k = t;
        bool active = (k <= 20);
        bool masked = false;
        int srcv = v;
        float lg = -FLT_MAX;
        if (active) {
            int s;
            if (k < 20) { s = g_topk[n * TK + k]; masked = (s == n); }
            else        { s = n; }                          // appended self-loop
            srcv = b * Nn + s;
            float L0 = g_ai[v] + g_ei[n] + g_aj[srcv] + g_ej[s];
            L0 = (L0 >= 0.f) ? L0 : 0.2f * L0;              // LeakyReLU(0.2)
            lg = masked ? -FLT_MAX : L0;                    // self-edge -> -inf
        }
        float m = lg;
#pragma unroll
        for (int off = 16; off; off >>= 1) m = fmaxf(m, __shfl_xor_sync(0xffffffffu, m, off));
        float e = (active && !masked) ? expf(lg - m) : 0.f;
        float den = e;
#pragma unroll
        for (int off = 16; off; off >>= 1) den += __shfl_xor_sync(0xffffffffu, den, off);
        if (active) { s_al[grp][k] = e / den; s_sr[grp][k] = srcv; }
    }
    __syncthreads();
    float acc = gnnb[t];
#pragma unroll
    for (int k = 0; k < 21; k++)
        acc += s_al[grp][k] * g_h[(size_t)s_sr[grp][k] * Dn + t];
    g_out[(size_t)v * Dn + t] = acc;
}

// ---------------- K5: BN1 block partials ---------------------------------------
__global__ __launch_bounds__(256) void k5_bn1p() {
    int r0 = blockIdx.x * 128;                  // 256 blocks
    int d = threadIdx.x & 63, rr = threadIdx.x >> 6;
    float s = 0.f, sq = 0.f;
    for (int r = r0 + rr; r < r0 + 128; r += 4) {
        float x = g_out[(size_t)r * 64 + d];
        s += x; sq += x * x;
    }
    __shared__ float rs[256], rq[256];
    rs[threadIdx.x] = s; rq[threadIdx.x] = sq;
    __syncthreads();
    if (threadIdx.x < 64) {
        int i = threadIdx.x;
        g_p1[blockIdx.x * 128 + i]      = rs[i] + rs[i + 64] + rs[i + 128] + rs[i + 192];
        g_p1[blockIdx.x * 128 + 64 + i] = rq[i] + rq[i + 64] + rq[i + 128] + rq[i + 192];
    }
}

__global__ __launch_bounds__(256) void k5b_bn1f(const float* __restrict__ g1v,
                                                const float* __restrict__ b1v) {
    int d = threadIdx.x & 63, q = threadIdx.x >> 6;   // 4 slices of 64 partials
    float s = 0.f, sq = 0.f;
    for (int p = q * 64; p < q * 64 + 64; p++) { s += g_p1[p * 128 + d]; sq += g_p1[p * 128 + 64 + d]; }
    __shared__ float rs[256], rq[256];
    rs[threadIdx.x] = s; rq[threadIdx.x] = sq;
    __syncthreads();
    if (threadIdx.x < 64) {
        s  = rs[d] + rs[d + 64] + rs[d + 128] + rs[d + 192];
        sq = rq[d] + rq[d + 64] + rq[d + 128] + rq[d + 192];
        float mean = s / (float)NNODE;
        float var = sq / (float)NNODE - mean * mean;
        float rstd = 1.f / sqrtf(var + BN_EPS);
        float sA = rstd * g1v[d];
        g_bn1f[d] = sA; g_bn1f[64 + d] = b1v[d] - mean * sA;
    }
}

// ---------------- K6: BN2 partials over xg (computed on the fly, no store) ------
__global__ __launch_bounds__(256) void k6_xg(const float* __restrict__ emb) {
    int d = threadIdx.x & 63;
    float sA = g_bn1f[d], sB = g_bn1f[64 + d];
    float s = 0.f, sq = 0.f;
    for (size_t e = blockIdx.x * 256 + threadIdx.x; e < (size_t)NNODE * 64; e += 512 * 256) {
        float x = g_out[e];
        float val = fmaxf(fmaf(x, sA, sB), 0.f);
        float xg = val * emb[(((int)(e >> 6)) & 1023) * 64 + d];
        s += xg; sq += xg * xg;
    }
    __shared__ float rs[256], rq[256];
    rs[threadIdx.x] = s; rq[threadIdx.x] = sq;
    __syncthreads();
    if (threadIdx.x < 64) {
        int i = threadIdx.x;
        g_p2[blockIdx.x * 128 + i]      = rs[i] + rs[i + 64] + rs[i + 128] + rs[i + 192];
        g_p2[blockIdx.x * 128 + 64 + i] = rq[i] + rq[i + 64] + rq[i + 128] + rq[i + 192];
    }
}

__global__ __launch_bounds__(256) void k6b_bn2f(const float* __restrict__ g2v,
                                                const float* __restrict__ b2v) {
    int d = threadIdx.x & 63, q = threadIdx.x >> 6;   // 4 slices of 128 partials
    float s = 0.f, sq = 0.f;
    for (int p = q * 128; p < q * 128 + 128; p++) { s += g_p2[p * 128 + d]; sq += g_p2[p * 128 + 64 + d]; }
    __shared__ float rs[256], rq[256];
    rs[threadIdx.x] = s; rq[threadIdx.x] = sq;
    __syncthreads();
    if (threadIdx.x < 64) {
        s  = rs[d] + rs[d + 64] + rs[d + 128] + rs[d + 192];
        sq = rq[d] + rq[d + 64] + rq[d + 128] + rq[d + 192];
        float mean = s / (float)NNODE;
        float var = sq / (float)NNODE - mean * mean;
        float rstd = 1.f / sqrtf(var + BN_EPS);
        float sA = rstd * g2v[d];
        g_bn2f[d] = sA; g_bn2f[64 + d] = b2v[d] - mean * sA;
    }
}

// ---------------- K7: recompute xg, apply BN2 + relu + projection -> o ----------
__global__ __launch_bounds__(256) void k7_proj(const float* __restrict__ emb,
                                               const float* __restrict__ outW,
                                               const float* __restrict__ outb,
                                               float* __restrict__ dout) {
    int w = threadIdx.x >> 5, lane = threadIdx.x & 31;
    int v = blockIdx.x * 8 + w;                 // 4096 blocks
    int n = v & 1023;
    float y = 0.f;
#pragma unroll
    for (int q = 0; q < 2; q++) {
        int d = lane + q * 32;
        float xo = g_out[(size_t)v * 64 + d];
        float val = fmaxf(fmaf(xo, g_bn1f[d], g_bn1f[64 + d]), 0.f);   // same op order as k6
        float xg = val * emb[n * 64 + d];
        y += fmaxf(fmaf(xg, g_bn2f[d], g_bn2f[64 + d]), 0.f) * outW[d];
    }
#pragma unroll
    for (int off = 16; off; off >>= 1) y += __shfl_xor_sync(0xffffffffu, y, off);
    if (lane == 0) dout[v] = y + outb[0];
}

// ---------------- launch --------------------------------------------------------
extern "C" void kernel_launch(void* const* d_in, const int* in_sizes, int n_in,
                              void* d_out, int out_size) {
    const float* x        = (const float*)d_in[0];
    const float* emb      = (const float*)d_in[1];
    const float* linW     = (const float*)d_in[2];
    const float* att_i    = (const float*)d_in[3];
    const float* att_j    = (const float*)d_in[4];
    const float* att_em_i = (const float*)d_in[5];
    const float* att_em_j = (const float*)d_in[6];
    const float* gnnb     = (const float*)d_in[7];
    const float* g1       = (const float*)d_in[8];
    const float* b1       = (const float*)d_in[9];
    const float* g2       = (const float*)d_in[10];
    const float* b2       = (const float*)d_in[11];
    const float* outW     = (const float*)d_in[12];
    const float* outb     = (const float*)d_in[13];
    float* out = (float*)d_out;

    // one-time host-side resources (created on the first, non-captured call;
    // identical captured work on every call; no device allocation)
    static cudaStream_t s1 = nullptr;
    static cudaEvent_t  evA = nullptr, evB = nullptr, ev1 = nullptr;
    static bool init_ok = false;
    static bool init_done = false;
    if (!init_done) {
        init_done = true;
        init_ok = (cudaStreamCreateWithFlags(&s1, cudaStreamNonBlocking) == cudaSuccess) &&
                  (cudaEventCreateWithFlags(&evA, cudaEventDisableTiming) == cudaSuccess) &&
                  (cudaEventCreateWithFlags(&evB, cudaEventDisableTiming) == cudaSuccess) &&
                  (cudaEventCreateWithFlags(&ev1, cudaEventDisableTiming) == cudaSuccess);
    }
    cudaStream_t sb = init_ok ? s1 : (cudaStream_t)0;   // fallback: serialize on default

    k1_stats<<<dim3(4, 32, 8), 256>>>(x);                        // (1) default stream
    k1b_fin <<<128, 256>>>(x, out);                              // (2)
    if (init_ok) { cudaEventRecord(evA, 0); cudaStreamWaitEvent(sb, evA, 0); }
    k1c_S   <<<64, 256, 0, sb>>>(linW);                          // (3) side stream
    if (init_ok) { cudaEventRecord(evB, sb); cudaStreamWaitEvent(0, evB, 0); }
    k2_gemm <<<512, 256>>>(x, linW, att_i, att_j);               // (4) <- profiled slot
    k3a_emb <<<128, 256, 0, sb>>>(emb, att_em_i, att_em_j);      // (5) emb chain (|| k2)
    k3b1_cos<<<dim3(16, 16), 256, 0, sb>>>(emb);                 // (6)
    k3b2_topk<<<1024, 1024, 0, sb>>>();                          // (7)
    if (init_ok) { cudaEventRecord(ev1, sb); cudaStreamWaitEvent(0, ev1, 0); }

    k4_agg  <<<8192, 256>>>(gnnb);                               // join
    k5_bn1p <<<256, 256>>>();
    k5b_bn1f<<<1, 256>>>(g1, b1);
    k6_xg   <<<512, 256>>>(emb);
    k6b_bn2f<<<1, 256>>>(g2, b2);
    k7_proj <<<4096, 256>>>(emb, outW, outb, out);
}

// round 15
// speedup vs baseline: 1.0171x; 1.0171x over previous
#include <cuda_runtime.h>
#include <math.h>
#include <float.h>

#define Bn 32
#define Ln 512
#define Nn 1024
#define Dn 64
#define TK 20
#define NNODE 32768           // B*N = 32*1024 (== L*64)
#define BN_EPS 1e-5f

typedef unsigned long long ull;

// ---------------- scratch (static device globals; no allocation) ----------------
__device__ __align__(16) float4 g_ps4 [8*8192];   // partial sums  (8 l-chunks, float4 over n)
__device__ __align__(16) float4 g_psq4[8*8192];   // partial sumsq
__device__ __align__(16) float  g_scale[NNODE];   // rstd per (b,n)
__device__ __align__(16) float  g_shift[NNODE];   // -mean*rstd
__device__ __align__(16) float  g_S   [64*64];    // shift @ W bias (row-in-l, d)
__device__ __align__(16) float  g_h  [NNODE*Dn];  // GEMM output (8MB)
__device__ float  g_cos[Nn*Nn];       // cosine matrix (4MB)
__device__ float  g_nrm[Nn];
__device__ float  g_ei [Nn];
__device__ float  g_ej [Nn];
__device__ int    g_topk[Nn*TK];
__device__ float  g_ai [NNODE];
__device__ float  g_aj [NNODE];
__device__ float  g_out[NNODE*Dn];    // aggregated (8MB)
__device__ float  g_p1 [256*2*Dn];    // BN1 block partials [256][128]
__device__ float  g_p2 [512*2*Dn];    // BN2 block partials [512][128]
__device__ float  g_bn1f[2*Dn];       // BN1 scale/shift
__device__ float  g_bn2f[2*Dn];       // BN2 scale/shift

// ---------------- K1: per-(b,n) sum/sumsq over L (vectorized, l-split) ----------
__global__ __launch_bounds__(256) void k1_stats(const float* __restrict__ x) {
    int nb = blockIdx.x;                       // 4  (n-chunk of 256)
    int b  = blockIdx.y;                       // 32
    int lc = blockIdx.z;                       // 8  (l-chunk of 64)
    int g  = threadIdx.x & 63;                 // float4 group over n
    int lq = threadIdx.x >> 6;                 // 4 l-slices of 16
    const float4* p = (const float4*)(x + ((size_t)b * Ln + (size_t)lc * 64 + lq * 16) * Nn
                                        + nb * 256 + g * 4);
    float4 s4 = make_float4(0.f, 0.f, 0.f, 0.f);
    float4 q4 = make_float4(0.f, 0.f, 0.f, 0.f);
#pragma unroll
    for (int i = 0; i < 16; i++) {
        float4 v = p[(size_t)i * (Nn / 4)];
        s4.x += v.x; s4.y += v.y; s4.z += v.z; s4.w += v.w;
        q4.x += v.x * v.x; q4.y += v.y * v.y; q4.z += v.z * v.z; q4.w += v.w * v.w;
    }
    __shared__ float4 ss[4][64], qq[4][64];
    ss[lq][g] = s4; qq[lq][g] = q4;
    __syncthreads();
    if (threadIdx.x < 64) {
        int i = threadIdx.x;
        float4 a0 = ss[0][i], a1 = ss[1][i], a2 = ss[2][i], a3 = ss[3][i];
        float4 b0 = qq[0][i], b1 = qq[1][i], b2 = qq[2][i], b3 = qq[3][i];
        float4 S = make_float4(a0.x+a1.x+a2.x+a3.x, a0.y+a1.y+a2.y+a3.y,
                               a0.z+a1.z+a2.z+a3.z, a0.w+a1.w+a2.w+a3.w);
        float4 Q = make_float4(b0.x+b1.x+b2.x+b3.x, b0.y+b1.y+b2.y+b3.y,
                               b0.z+b1.z+b2.z+b3.z, b0.w+b1.w+b2.w+b3.w);
        int m4 = b * 256 + nb * 64 + i;
        g_ps4 [lc * 8192 + m4] = S;
        g_psq4[lc * 8192 + m4] = Q;
    }
}

// ---------------- K1b: finalize scale/shift + write gt -------------------------
__global__ __launch_bounds__(256) void k1b_fin(const float* __restrict__ x,
                                               float* __restrict__ dout) {
    int m = blockIdx.x * 256 + threadIdx.x;    // 128 blocks -> 32768
    const float* psF = (const float*)g_ps4;
    const float* qqF = (const float*)g_psq4;
    float s = 0.f, sq = 0.f;
#pragma unroll
    for (int lc = 0; lc < 8; lc++) { s += psF[lc * 32768 + m]; sq += qqF[lc * 32768 + m]; }
    float mean = s * (1.f / 512.f);
    float var  = sq * (1.f / 512.f) - mean * mean;   // NO eps (matches reference)
    float rstd = 1.f / sqrtf(var);
    g_scale[m] = rstd;
    g_shift[m] = -mean * rstd;
    int b = m >> 10, n = m & 1023;
    float xl = x[(size_t)b * Ln * Nn + (size_t)(Ln - 1) * Nn + n];
    float gv = xl * rstd - mean * rstd;
    if (!isfinite(gv)) gv = 0.f;                     // nan_to_num
    dout[NNODE + m] = gv;                            // gt is second half of output
}

// ---------------- K1c: S[c][d] = sum_k shift[c*512+k] * W[k][d] ----------------
__global__ __launch_bounds__(256) void k1c_S(const float* __restrict__ W) {
    int c = blockIdx.x;                        // 64
    int d = threadIdx.x & 63, kq = threadIdx.x >> 6;
    float acc = 0.f;
    for (int k = kq * 128; k < kq * 128 + 128; k++)
        acc = fmaf(g_shift[c * 512 + k], W[k * 64 + d], acc);
    __shared__ float rs[4][64];
    rs[kq][d] = acc;
    __syncthreads();
    if (threadIdx.x < 64)
        g_S[c * 64 + threadIdx.x] = rs[0][threadIdx.x] + rs[1][threadIdx.x]
                                  + rs[2][threadIdx.x] + rs[3][threadIdx.x];
}

// ---------------- K2: h = x*scale @ W + S  + fused ai/aj epilogue --------------
// M-tile 128 (2 timesteps) per block, 8 rows x 8 cols per thread, f32x2 FMA.
// A smem XOR-swizzled (zero padding): float idx = (c*32 + (c&7)*4) ^ (g*4).
#define FMA2(d, a, b) asm("fma.rn.f32x2 %0, %1, %2, %0;" : "+l"(d) : "l"(a), "l"(b))
#define PACKDUP(d, v) asm("mov.b64 %0, {%1, %1};" : "=l"(d) : "r"(__float_as_uint(v)))

__global__ __launch_bounds__(256) void k2_gemm(const float* __restrict__ x,
                                               const float* __restrict__ W,
                                               const float* __restrict__ ati,
                                               const float* __restrict__ atj) {
    int l0 = blockIdx.x * 2;                   // 256 blocks, 2 timesteps each
    int tid = threadIdx.x;
    __shared__ __align__(16) float As[2][128 * 32];   // swizzled, 32KB
    __shared__ __align__(16) ull   Bs[2][32][32];     // 16KB
    ull acc2[8][2] = {};                        // 8 rows (ty+16r) x 2 f32x2 pairs
    int ty = tid >> 4, tx = tid & 15;

    float4 xv[4], wv[2], xv2[4], wv2[2];

    // ---- loaders: A = x*scale (4 float4/thread), B = W (2 float4/thread) ----
    auto load_tile = [&](int kt, float4* xr, float4* wr) {
#pragma unroll
        for (int r = 0; r < 4; r++) {
            int a = tid + r * 256;              // [0,1024)
            int c = a >> 3, ch = a & 7;         // row c (0..127), k-chunk ch
            int l = l0 + (c >> 6), c64 = c & 63;
            if (l == Ln - 1) {                  // zeroed last timestep
                xr[r] = make_float4(0.f, 0.f, 0.f, 0.f);
            } else {
                int m = c64 * 512 + kt * 32 + ch * 4;
                int bb = m >> 10, nn = m & 1023;
                float4 xx = *(const float4*)(x + (size_t)bb * (Ln * Nn) + (size_t)l * Nn + nn);
                float4 ss = *(const float4*)(g_scale + m);
                xr[r] = make_float4(xx.x * ss.x, xx.y * ss.y, xx.z * ss.z, xx.w * ss.w);
            }
        }
#pragma unroll
        for (int r = 0; r < 2; r++) {
            int a = tid + r * 256;              // [0,512)
            int k2i = a >> 4, dq = a & 15;
            wr[r] = *(const float4*)(W + (size_t)(kt * 32 + k2i) * 64 + dq * 4);
        }
    };
    auto store_tile = [&](int buf, const float4* xr, const float4* wr) {
#pragma unroll
        for (int r = 0; r < 4; r++) {
            int a = tid + r * 256;
            int c = a >> 3, ch = a & 7;
            int idx = (c * 32 + (c & 7) * 4) ^ (ch * 4);       // swizzled float idx
            *(float4*)&As[buf][idx] = xr[r];
        }
#pragma unroll
        for (int r = 0; r < 2; r++) {
            int a = tid + r * 256;
            int k2i = a >> 4, dq = a & 15;
            *(float4*)((float*)&Bs[buf][k2i][0] + dq * 4) = wr[r];
        }
    };

    // precompute per-row swizzle bases (c = ty + 16r)
    int abase[8];
#pragma unroll
    for (int r = 0; r < 8; r++) {
        int c = ty + 16 * r;
        abase[r] = c * 32 + (c & 7) * 4;
    }

    load_tile(0, xv, wv);
    store_tile(0, xv, wv);
    __syncthreads();

    for (int kt = 0; kt < 16; kt++) {
        int buf = kt & 1;
        if (kt < 15) load_tile(kt + 1, xv2, wv2);   // prefetch overlaps compute

        const float* AsF = As[buf];
        const ull (*Bsb)[32] = Bs[buf];
#pragma unroll
        for (int g = 0; g < 8; g++) {           // j group = g*4 .. g*4+3
            ulonglong2 B0 = *(const ulonglong2*)&Bsb[g * 4 + 0][tx * 2];
            ulonglong2 B1 = *(const ulonglong2*)&Bsb[g * 4 + 1][tx * 2];
            ulonglong2 B2 = *(const ulonglong2*)&Bsb[g * 4 + 2][tx * 2];
            ulonglong2 B3 = *(const ulonglong2*)&Bsb[g * 4 + 3][tx * 2];
#pragma unroll
            for (int r = 0; r < 8; r++) {
                float4 Ar = *(const float4*)&AsF[abase[r] ^ (g * 4)];
                ull aa;
                PACKDUP(aa, Ar.x); FMA2(acc2[r][0], aa, B0.x); FMA2(acc2[r][1], aa, B0.y);
                PACKDUP(aa, Ar.y); FMA2(acc2[r][0], aa, B1.x); FMA2(acc2[r][1], aa, B1.y);
                PACKDUP(aa, Ar.z); FMA2(acc2[r][0], aa, B2.x); FMA2(acc2[r][1], aa, B2.y);
                PACKDUP(aa, Ar.w); FMA2(acc2[r][0], aa, B3.x); FMA2(acc2[r][1], aa, B3.y);
            }
        }
        __syncthreads();                        // all reads of buf done
        if (kt < 15) {
            store_tile(buf ^ 1, xv2, wv2);      // write other buffer
            __syncthreads();                    // publish before next compute
        }
    }

    // ---- epilogue: +S bias (l<511), write h, fused ai/aj dots ----
    float4 wi = *(const float4*)&ati[tx * 4];
    float4 wj = *(const float4*)&atj[tx * 4];
#pragma unroll
    for (int r = 0; r < 8; r++) {
        int c = ty + 16 * r;
        int l = l0 + (c >> 6), c64 = c & 63;
        float4 o;
        if (l == Ln - 1) {
            o = make_float4(0.f, 0.f, 0.f, 0.f);
        } else {
            float4 Sb = *(const float4*)&g_S[c64 * 64 + tx * 4];
            float2 p0 = *(float2*)&acc2[r][0];
            float2 p1 = *(float2*)&acc2[r][1];
            o = make_float4(p0.x + Sb.x, p0.y + Sb.y, p1.x + Sb.z, p1.y + Sb.w);
        }
        *(float4*)&g_h[((size_t)l * 64 + c64) * 64 + tx * 4] = o;
        float di = o.x * wi.x + o.y * wi.y + o.z * wi.z + o.w * wi.w;
        float dj = o.x * wj.x + o.y * wj.y + o.z * wj.z + o.w * wj.w;
#pragma unroll
        for (int off = 8; off; off >>= 1) {
            di += __shfl_xor_sync(0xffffffffu, di, off);
            dj += __shfl_xor_sync(0xffffffffu, dj, off);
        }
        if (tx == 0) {
            g_ai[l * 64 + c64] = di;
            g_aj[l * 64 + c64] = dj;
        }
    }
}

// ---------------- K3a: emb norms + att_em dots (warp per n) --------------------
__global__ __launch_bounds__(256) void k3a_emb(const float* __restrict__ emb,
                                               const float* __restrict__ aei,
                                               const float* __restrict__ aej) {
    int w = (blockIdx.x * 256 + threadIdx.x) >> 5;  // 128 blocks -> 1024 warps
    int lane = threadIdx.x & 31;
    float e1 = emb[w * 64 + lane], e2 = emb[w * 64 + 32 + lane];
    float sq = e1 * e1 + e2 * e2;
    float di = e1 * aei[lane] + e2 * aei[lane + 32];
    float dj = e1 * aej[lane] + e2 * aej[lane + 32];
#pragma unroll
    for (int off = 16; off; off >>= 1) {
        sq += __shfl_xor_sync(0xffffffffu, sq, off);
        di += __shfl_xor_sync(0xffffffffu, di, off);
        dj += __shfl_xor_sync(0xffffffffu, dj, off);
    }
    if (lane == 0) { g_nrm[w] = sqrtf(sq); g_ei[w] = di; g_ej[w] = dj; }
}

// ---------------- K3b1: cosine matrix (64x64 tiles) ----------------------------
__global__ __launch_bounds__(256) void k3b1_cos(const float* __restrict__ emb) {
    __shared__ float Ae[64][65];
    __shared__ float Be[64][65];
    int tid = threadIdx.x;
    int by = blockIdx.y, bx = blockIdx.x;
#pragma unroll
    for (int r = 0; r < 16; r++) {
        int a = tid + r * 256;
        int row = a >> 6, col = a & 63;
        Ae[row][col] = emb[(by * 64 + row) * 64 + col];
        Be[row][col] = emb[(bx * 64 + row) * 64 + col];
    }
    __syncthreads();
    int ty = tid >> 4, tx = tid & 15;
    float acc[4][4] = {};
#pragma unroll 8
    for (int d = 0; d < 64; d++) {
        float av[4], bv[4];
#pragma unroll
        for (int r = 0; r < 4; r++) { av[r] = Ae[ty * 4 + r][d]; bv[r] = Be[tx * 4 + r][d]; }
#pragma unroll
        for (int r = 0; r < 4; r++)
#pragma unroll
            for (int s2 = 0; s2 < 4; s2++)
                acc[r][s2] = fmaf(av[r], bv[s2], acc[r][s2]);
    }
#pragma unroll
    for (int r = 0; r < 4; r++)
#pragma unroll
        for (int s2 = 0; s2 < 4; s2++) {
            int rg = by * 64 + ty * 4 + r, cg = bx * 64 + tx * 4 + s2;
            g_cos[rg * 1024 + cg] = acc[r][s2] / (g_nrm[rg] * g_nrm[cg]);
        }
}

// ---------------- K3b2: top-20 per row, shuffle argmax (JAX tie rule) -----------
__global__ __launch_bounds__(1024) void k3b2_topk() {
    int r = blockIdx.x, t = threadIdx.x;
    int lane = t & 31, wid = t >> 5;
    __shared__ float swv[32];
    __shared__ int   swi[32];
    __shared__ int   s_best;
    float v = g_cos[r * 1024 + t];
#pragma unroll 1
    for (int it = 0; it < TK; it++) {
        float mv = v; int mi = t;
#pragma unroll
        for (int off = 16; off; off >>= 1) {
            float ov = __shfl_xor_sync(0xffffffffu, mv, off);
            int   oi = __shfl_xor_sync(0xffffffffu, mi, off);
            if (ov > mv || (ov == mv && oi < mi)) { mv = ov; mi = oi; }
        }
        if (lane == 0) { swv[wid] = mv; swi[wid] = mi; }
        __syncthreads();
        if (wid == 0) {
            float mv2 = swv[lane]; int mi2 = swi[lane];
#pragma unroll
            for (int off = 16; off; off >>= 1) {
                float ov = __shfl_xor_sync(0xffffffffu, mv2, off);
                int   oi = __shfl_xor_sync(0xffffffffu, mi2, off);
                if (ov > mv2 || (ov == mv2 && oi < mi2)) { mv2 = ov; mi2 = oi; }
            }
            if (lane == 0) { g_topk[r * TK + it] = mi2; s_best = mi2; }
        }
        __syncthreads();
        if (t == s_best) v = -FLT_MAX;
    }
}

// ---------------- K4: per-node attention softmax + aggregation -----------------
__global__ __launch_bounds__(256) void k4_agg(const float* __restrict__ gnnb) {
    int grp = threadIdx.x >> 6;                 // 4 dst nodes / block
    int t   = threadIdx.x & 63;
    int v = blockIdx.x * 4 + grp;               // 8192 blocks
    int b = v >> 10, n = v & 1023;
    __shared__ float s_al[4][21];
    __shared__ int   s_sr[4][21];
    if (t < 32) {
        int k = t;
        bool active = (k <= 20);
        bool masked = false;
        int srcv = v;
        float lg = -FLT_MAX;
        if (active) {
            int s;
            if (k < 20) { s = g_topk[n * TK + k]; masked = (s == n); }
            else        { s = n; }                          // appended self-loop
            srcv = b * Nn + s;
            float L0 = g_ai[v] + g_ei[n] + g_aj[srcv] + g_ej[s];
            L0 = (L0 >= 0.f) ? L0 : 0.2f * L0;              // LeakyReLU(0.2)
            lg = masked ? -FLT_MAX : L0;                    // self-edge -> -inf
        }
        float m = lg;
#pragma unroll
        for (int off = 16; off; off >>= 1) m = fmaxf(m, __shfl_xor_sync(0xffffffffu, m, off));
        float e = (active && !masked) ? expf(lg - m) : 0.f;
        float den = e;
#pragma unroll
        for (int off = 16; off; off >>= 1) den += __shfl_xor_sync(0xffffffffu, den, off);
        if (active) { s_al[grp][k] = e / den; s_sr[grp][k] = srcv; }
    }
    __syncthreads();
    float acc = gnnb[t];
#pragma unroll
    for (int k = 0; k < 21; k++)
        acc += s_al[grp][k] * g_h[(size_t)s_sr[grp][k] * Dn + t];
    g_out[(size_t)v * Dn + t] = acc;
}

// ---------------- K5: BN1 block partials ---------------------------------------
__global__ __launch_bounds__(256) void k5_bn1p() {
    int r0 = blockIdx.x * 128;                  // 256 blocks
    int d = threadIdx.x & 63, rr = threadIdx.x >> 6;
    float s = 0.f, sq = 0.f;
    for (int r = r0 + rr; r < r0 + 128; r += 4) {
        float x = g_out[(size_t)r * 64 + d];
        s += x; sq += x * x;
    }
    __shared__ float rs[256], rq[256];
    rs[threadIdx.x] = s; rq[threadIdx.x] = sq;
    __syncthreads();
    if (threadIdx.x < 64) {
        int i = threadIdx.x;
        g_p1[blockIdx.x * 128 + i]      = rs[i] + rs[i + 64] + rs[i + 128] + rs[i + 192];
        g_p1[blockIdx.x * 128 + 64 + i] = rq[i] + rq[i + 64] + rq[i + 128] + rq[i + 192];
    }
}

__global__ __launch_bounds__(256) void k5b_bn1f(const float* __restrict__ g1v,
                                                const float* __restrict__ b1v) {
    int d = threadIdx.x & 63, q = threadIdx.x >> 6;   // 4 slices of 64 partials
    float s = 0.f, sq = 0.f;
    for (int p = q * 64; p < q * 64 + 64; p++) { s += g_p1[p * 128 + d]; sq += g_p1[p * 128 + 64 + d]; }
    __shared__ float rs[256], rq[256];
    rs[threadIdx.x] = s; rq[threadIdx.x] = sq;
    __syncthreads();
    if (threadIdx.x < 64) {
        s  = rs[d] + rs[d + 64] + rs[d + 128] + rs[d + 192];
        sq = rq[d] + rq[d + 64] + rq[d + 128] + rq[d + 192];
        float mean = s / (float)NNODE;
        float var = sq / (float)NNODE - mean * mean;
        float rstd = 1.f / sqrtf(var + BN_EPS);
        float sA = rstd * g1v[d];
        g_bn1f[d] = sA; g_bn1f[64 + d] = b1v[d] - mean * sA;
    }
}

// ---------------- K6: BN2 partials over xg (computed on the fly, no store) ------
__global__ __launch_bounds__(256) void k6_xg(const float* __restrict__ emb) {
    int d = threadIdx.x & 63;
    float sA = g_bn1f[d], sB = g_bn1f[64 + d];
    float s = 0.f, sq = 0.f;
    for (size_t e = blockIdx.x * 256 + threadIdx.x; e < (size_t)NNODE * 64; e += 512 * 256) {
        float x = g_out[e];
        float val = fmaxf(fmaf(x, sA, sB), 0.f);
        float xg = val * emb[(((int)(e >> 6)) & 1023) * 64 + d];
        s += xg; sq += xg * xg;
    }
    __shared__ float rs[256], rq[256];
    rs[threadIdx.x] = s; rq[threadIdx.x] = sq;
    __syncthreads();
    if (threadIdx.x < 64) {
        int i = threadIdx.x;
        g_p2[blockIdx.x * 128 + i]      = rs[i] + rs[i + 64] + rs[i + 128] + rs[i + 192];
        g_p2[blockIdx.x * 128 + 64 + i] = rq[i] + rq[i + 64] + rq[i + 128] + rq[i + 192];
    }
}

__global__ __launch_bounds__(256) void k6b_bn2f(const float* __restrict__ g2v,
                                                const float* __restrict__ b2v) {
    int d = threadIdx.x & 63, q = threadIdx.x >> 6;   // 4 slices of 128 partials
    float s = 0.f, sq = 0.f;
    for (int p = q * 128; p < q * 128 + 128; p++) { s += g_p2[p * 128 + d]; sq += g_p2[p * 128 + 64 + d]; }
    __shared__ float rs[256], rq[256];
    rs[threadIdx.x] = s; rq[threadIdx.x] = sq;
    __syncthreads();
    if (threadIdx.x < 64) {
        s  = rs[d] + rs[d + 64] + rs[d + 128] + rs[d + 192];
        sq = rq[d] + rq[d + 64] + rq[d + 128] + rq[d + 192];
        float mean = s / (float)NNODE;
        float var = sq / (float)NNODE - mean * mean;
        float rstd = 1.f / sqrtf(var + BN_EPS);
        float sA = rstd * g2v[d];
        g_bn2f[d] = sA; g_bn2f[64 + d] = b2v[d] - mean * sA;
    }
}

// ---------------- K7: recompute xg, apply BN2 + relu + projection -> o ----------
__global__ __launch_bounds__(256) void k7_proj(const float* __restrict__ emb,
                                               const float* __restrict__ outW,
                                               const float* __restrict__ outb,
                                               float* __restrict__ dout) {
    int w = threadIdx.x >> 5, lane = threadIdx.x & 31;
    int v = blockIdx.x * 8 + w;                 // 4096 blocks
    int n = v & 1023;
    float y = 0.f;
#pragma unroll
    for (int q = 0; q < 2; q++) {
        int d = lane + q * 32;
        float xo = g_out[(size_t)v * 64 + d];
        float val = fmaxf(fmaf(xo, g_bn1f[d], g_bn1f[64 + d]), 0.f);   // same op order as k6
        float xg = val * emb[n * 64 + d];
        y += fmaxf(fmaf(xg, g_bn2f[d], g_bn2f[64 + d]), 0.f) * outW[d];
    }
#pragma unroll
    for (int off = 16; off; off >>= 1) y += __shfl_xor_sync(0xffffffffu, y, off);
    if (lane == 0) dout[v] = y + outb[0];
}

// ---------------- launch --------------------------------------------------------
extern "C" void kernel_launch(void* const* d_in, const int* in_sizes, int n_in,
                              void* d_out, int out_size) {
    const float* x        = (const float*)d_in[0];
    const float* emb      = (const float*)d_in[1];
    const float* linW     = (const float*)d_in[2];
    const float* att_i    = (const float*)d_in[3];
    const float* att_j    = (const float*)d_in[4];
    const float* att_em_i = (const float*)d_in[5];
    const float* att_em_j = (const float*)d_in[6];
    const float* gnnb     = (const float*)d_in[7];
    const float* g1       = (const float*)d_in[8];
    const float* b1       = (const float*)d_in[9];
    const float* g2       = (const float*)d_in[10];
    const float* b2       = (const float*)d_in[11];
    const float* outW     = (const float*)d_in[12];
    const float* outb     = (const float*)d_in[13];
    float* out = (float*)d_out;

    // one-time host-side resources (created on the first, non-captured call)
    static cudaStream_t s1 = nullptr;
    static cudaEvent_t  ev0 = nullptr, ev1 = nullptr;
    static bool init_ok = false;
    static bool init_done = false;
    if (!init_done) {
        init_done = true;
        init_ok = (cudaStreamCreateWithFlags(&s1, cudaStreamNonBlocking) == cudaSuccess) &&
                  (cudaEventCreateWithFlags(&ev0, cudaEventDisableTiming) == cudaSuccess) &&
                  (cudaEventCreateWithFlags(&ev1, cudaEventDisableTiming) == cudaSuccess);
    }
    cudaStream_t sb = init_ok ? s1 : (cudaStream_t)0;   // fallback: serialize on default

    if (init_ok) { cudaEventRecord(ev0, 0); cudaStreamWaitEvent(sb, ev0, 0); }

    k1_stats<<<dim3(4, 32, 8), 256>>>(x);                        // (1) default stream
    k1b_fin <<<128, 256>>>(x, out);                              // (2)
    k1c_S   <<<64, 256>>>(linW);                                 // (3)
    k2_gemm <<<256, 256>>>(x, linW, att_i, att_j);               // (4) <- profiled slot
    k3a_emb <<<128, 256, 0, sb>>>(emb, att_em_i, att_em_j);      // (5) emb chain (|| k2)
    k3b1_cos<<<dim3(16, 16), 256, 0, sb>>>(emb);                 // (6)
    k3b2_topk<<<1024, 1024, 0, sb>>>();                          // (7)
    if (init_ok) { cudaEventRecord(ev1, sb); cudaStreamWaitEvent(0, ev1, 0); }

    k4_agg  <<<8192, 256>>>(gnnb);                               // join
    k5_bn1p <<<256, 256>>>();
    k5b_bn1f<<<1, 256>>>(g1, b1);
    k6_xg   <<<512, 256>>>(emb);
    k6b_bn2f<<<1, 256>>>(g2, b2);
    k7_proj <<<4096, 256>>>(emb, outW, outb, out);
}